// round 9
// baseline (speedup 1.0000x reference)
#include <cuda_runtime.h>

// QuixerCore — analytic collapse, 2-kernel chip-parallel version.
//
// Math (unchanged from the validated R8 kernel):
//  * CRX blocks are no-ops; only RY params [0..10] and [22..32] act.
//  * Each token unitary is a product of per-qubit RY rotations with half-angle
//    h[t][q] = (A[t][q] + A[t][q+22]) / 2, A = emb @ W.T + b.
//  * _apply_lcu's norm prefactor cancels -> acc = sum of 21 weighted product
//    states (1 + 4 + 16), with the ff unitary folded in as +h_ff[q].
//  * poly_norm and final normalization cancel in exps = raw / ||acc||^2.
//  * Expectations factorize over qubits: 231 pair overlaps x 11 qubits.
//
// k1 (22 CTAs): the 88 length-512 dot products via FFMA2 (fma.rn.f32x2),
//               one warp per (token, param); CTA0's warp 4 computes the lcu
//               normalizer and the 21 complex term weights.
// k2 (1 CTA):   half-angles -> __sincosf tables -> pair overlaps -> reduce.

namespace {

constexpr int NQ    = 11;
constexpr int NT    = 21;    // 1 + 4 + 16 product-state terms
constexpr int NPAIR = 231;   // NT*(NT+1)/2

__device__ float g_rawA[4 * 22];   // A[t][jj]; jj<11 -> param jj, else jj+11
__device__ float g_wre[NT];
__device__ float g_wim[NT];

__device__ __forceinline__ void ffma2(unsigned long long& acc,
                                      unsigned long long a,
                                      unsigned long long b) {
    asm("fma.rn.f32x2 %0, %1, %2, %0;" : "+l"(acc) : "l"(a), "l"(b));
}

// ---- k1: 88 dot products across 22 CTAs + weight precompute ----
__global__ void __launch_bounds__(160, 1) quixer_k1(
    const float* __restrict__ emb,   // [32,512]
    const float* __restrict__ W,     // [44,512]
    const float* __restrict__ bias,  // [44]
    const float* __restrict__ qc,    // [3]
    const float* __restrict__ lre,   // [32]
    const float* __restrict__ lim)   // [32]
{
    const int lane = threadIdx.x & 31;
    const int w    = threadIdx.x >> 5;
    const int c    = blockIdx.x;              // jj in [0,22)

    if (w < 4) {
        const int t = w;                      // token
        const int j = (c < NQ) ? c : (c + 11);
        const ulonglong2* e2 = reinterpret_cast<const ulonglong2*>(emb + t * 512);
        const ulonglong2* w2 = reinterpret_cast<const ulonglong2*>(W + j * 512);
        unsigned long long acc0 = 0ull, acc1 = 0ull;   // f32x2 (0,0)
        #pragma unroll
        for (int k = 0; k < 4; k++) {
            ulonglong2 a = e2[lane + 32 * k];
            ulonglong2 b = w2[lane + 32 * k];
            ffma2(acc0, a.x, b.x);
            ffma2(acc1, a.y, b.y);
        }
        float2 f0 = *reinterpret_cast<float2*>(&acc0);
        float2 f1 = *reinterpret_cast<float2*>(&acc1);
        float s = (f0.x + f0.y) + (f1.x + f1.y);
        #pragma unroll
        for (int o = 16; o; o >>= 1) s += __shfl_xor_sync(0xffffffffu, s, o);
        if (lane == 0) g_rawA[t * 22 + c] = s + bias[j];
    } else if (c == 0) {
        // warp 4, CTA 0: lcu normalizer S, then 21 complex weights (lanes 0..20)
        float v = hypotf(lre[lane], lim[lane]);   // 32 tokens, one per lane
        #pragma unroll
        for (int o = 16; o; o >>= 1) v += __shfl_xor_sync(0xffffffffu, v, o);
        const float invS = 1.f / fmaxf(v, 1e-8f); // butterfly: all lanes hold sum
        const int m = lane;
        if (m < NT) {
            float re, im;
            if (m == 0) {
                re = qc[0]; im = 0.f;
            } else if (m < 5) {
                int s4 = m - 1;
                float q1 = qc[1];
                re = q1 * lre[s4] * invS;
                im = q1 * lim[s4] * invS;
            } else {
                int idx = m - 5;
                int t = idx >> 2, s4 = idx & 3;
                float ar = lre[t] * invS, ai = lim[t] * invS;
                float br = lre[s4] * invS, bi = lim[s4] * invS;
                float q2 = qc[2];
                re = q2 * (ar * br - ai * bi);
                im = q2 * (ar * bi + ai * br);
            }
            g_wre[m] = re;
            g_wim[m] = im;
        }
    }
}

// ---- k2: tables, pair overlaps, reduction, output ----
__global__ void __launch_bounds__(256, 1) quixer_k2(
    const float* __restrict__ ffp,   // [44]
    float* __restrict__ out)         // [33]
{
    __shared__ float hh[4][NQ];
    __shared__ float sc[NT][NQ];
    __shared__ float ss[NT][NQ];
    __shared__ float wre[NT], wim[NT];
    __shared__ float part[34][8];

    const int tid  = threadIdx.x;
    const int lane = tid & 31;
    const int wid  = tid >> 5;

    // Issue ffp loads early so their latency overlaps the hh computation.
    int term = 0, qq = 0;
    float hbase = 0.f;
    if (tid < NT * NQ) {
        term = tid / NQ;
        qq   = tid - term * NQ;
        hbase = 0.5f * (ffp[qq] + ffp[qq + 22]);   // ff unitary folded in
    }
    if (tid < 4 * NQ) {
        int t = tid / NQ, q = tid - t * NQ;
        hh[t][q] = 0.5f * (g_rawA[t * 22 + q] + g_rawA[t * 22 + q + 11]);
    }
    if (tid >= 64 && tid < 64 + NT) {
        int m = tid - 64;
        wre[m] = g_wre[m];
        wim[m] = g_wim[m];
    }
    __syncthreads();

    if (tid < NT * NQ) {
        float h = hbase;
        if (term >= 1 && term < 5) {
            h += hh[term - 1][qq];
        } else if (term >= 5) {
            int idx = term - 5;
            h += hh[idx >> 2][qq] + hh[idx & 3][qq];
        }
        float cv, sv;
        __sincosf(h, &sv, &cv);
        sc[term][qq] = cv;
        ss[term][qq] = sv;
    }
    __syncthreads();

    // 231 term pairs, one per thread (8 warps x 32)
    {
        const int p = tid;
        const bool valid = (p < NPAIR);
        int a = 0, b = 0;
        if (valid) {
            int rem = p;
            while (rem >= NT - a) { rem -= NT - a; a++; }
            b = a + rem;                       // a <= b
        }

        float d[NQ], pre[NQ + 1];
        pre[0] = 1.f;
        #pragma unroll
        for (int q = 0; q < NQ; q++) {
            float cav = sc[a][q], sav = ss[a][q];
            float cbv = sc[b][q], sbv = ss[b][q];
            d[q] = cav * cbv + sav * sbv;
            pre[q + 1] = pre[q] * d[q];
        }

        float Wr, Wy;
        if (!valid) {
            Wr = 0.f; Wy = 0.f;
        } else if (a == b) {
            Wr = wre[a] * wre[a] + wim[a] * wim[a];           // |w_a|^2
            Wy = 0.f;
        } else {
            Wr =  2.f * (wre[a] * wre[b] + wim[a] * wim[b]);  //  2 Re(conj(wa) wb)
            Wy = -2.f * (wre[a] * wim[b] - wim[a] * wre[b]);  // -2 Im(conj(wa) wb)
        }

        float vals[34];
        vals[0] = Wr * pre[NQ];                 // ||acc||^2 contribution
        float suf = 1.f;
        #pragma unroll
        for (int q = NQ - 1; q >= 0; q--) {
            float cav = sc[a][q], sav = ss[a][q];
            float cbv = sc[b][q], sbv = ss[b][q];
            float mm = pre[q] * suf;            // Prod_{q' != q} d_{q'}
            vals[1 + 3 * q + 0] = Wr * (cav * sbv + sav * cbv) * mm;  // X
            vals[1 + 3 * q + 1] = Wy * (sav * cbv - cav * sbv) * mm;  // Y
            vals[1 + 3 * q + 2] = Wr * (cav * cbv - sav * sbv) * mm;  // Z
            suf *= d[q];
        }

        #pragma unroll
        for (int m = 0; m < 34; m++) {
            float v = vals[m];
            #pragma unroll
            for (int o = 16; o; o >>= 1) v += __shfl_xor_sync(0xffffffffu, v, o);
            if (lane == 0) part[m][wid] = v;
        }
    }
    __syncthreads();

    if (tid < 33) {
        float num = 0.f, den = 0.f;
        #pragma unroll
        for (int k = 0; k < 8; k++) {
            num += part[tid + 1][k];
            den += part[0][k];
        }
        out[tid] = num / den;
    }
}

}  // namespace

extern "C" void kernel_launch(void* const* d_in, const int* in_sizes, int n_in,
                              void* d_out, int out_size) {
    (void)in_sizes; (void)n_in; (void)out_size;
    quixer_k1<<<22, 160>>>(
        (const float*)d_in[0],   // tokens_emb [32,512]
        (const float*)d_in[1],   // W_angles   [44,512]
        (const float*)d_in[2],   // b_angles   [44]
        (const float*)d_in[3],   // qsvt_coeffs[3]
        (const float*)d_in[4],   // lcu_re     [32]
        (const float*)d_in[5]);  // lcu_im     [32]
    quixer_k2<<<1, 256>>>(
        (const float*)d_in[6],   // ff_params  [44]
        (float*)d_out);          // [33]
}